// round 17
// baseline (speedup 1.0000x reference)
#include <cuda_runtime.h>
#include <cuda_bf16.h>
#include <cstdint>
#include <math.h>

#define BB 8
#define TT 2048
#define DM 1024
#define NS 512
#define NPAD 640
#define NHW 520
#define KHW 576                 // padded K for GEMM2 (18 x 32)
#define ROWS (BB*TT)            // 16384
#define NCH 256                 // chunks of 8 steps
#define NSEG 8
#define CH_PER_SEG (NCH / NSEG) // 32
#define TSEG (TT / NSEG)        // 256 rows per batch per segment

// ---------------- scratch (static device globals; no dynamic alloc) ----------------
__device__ float g_P[ROWS * NPAD];              // GEMM1 output fp32
__device__ float g_C[ROWS * 64];                // C matrices (b,t,8,8)
__device__ float g_alpha[ROWS * 8];
__device__ float g_bpack[NPAD];                 // packed biases
__device__ float g_A[NS];
__device__ float g_W8[512];                     // W_d = V^T diag(a^d) U, d=0..7, [d][r][c]
__device__ float g_hcarry[BB * NS];             // h carry between scan segments
__device__ float g_wcarry[BB * 8];              // w carry between scan segments
__device__ __nv_bfloat16 g_xh[ROWS * DM];       // x split hi/lo, [M][K]
__device__ __nv_bfloat16 g_xl[ROWS * DM];
__device__ __nv_bfloat16 g_Wh[DM * NPAD];       // Wpack [K=1024][N=640] hi/lo
__device__ __nv_bfloat16 g_Wl[DM * NPAD];
__device__ __nv_bfloat16 g_hwh[ROWS * KHW];     // [h*alpha | alpha | 0pad] hi, bf16
__device__ __nv_bfloat16 g_hwl[ROWS * KHW];     // lo residual
__device__ __nv_bfloat16 g_W2h[KHW * DM];       // W2 [K=576][N=1024] hi/lo
__device__ __nv_bfloat16 g_W2l[KHW * DM];

// ---------------- helpers ----------------
__device__ __forceinline__ uint32_t smem_u32(const void* p) {
    uint32_t a;
    asm("{ .reg .u64 t; cvta.to.shared.u64 t, %1; cvt.u32.u64 %0, t; }" : "=r"(a) : "l"(p));
    return a;
}
__device__ __forceinline__ void cp16(uint32_t dst, const void* src) {
    asm volatile("cp.async.cg.shared.global [%0], [%1], 16;" :: "r"(dst), "l"(src));
}
__device__ __forceinline__ void ldsm4(uint32_t* r, uint32_t addr) {
    asm volatile("ldmatrix.sync.aligned.m8n8.x4.shared.b16 {%0,%1,%2,%3}, [%4];"
                 : "=r"(r[0]), "=r"(r[1]), "=r"(r[2]), "=r"(r[3]) : "r"(addr));
}
__device__ __forceinline__ void ldsm4t(uint32_t* r, uint32_t addr) {
    asm volatile("ldmatrix.sync.aligned.m8n8.x4.trans.shared.b16 {%0,%1,%2,%3}, [%4];"
                 : "=r"(r[0]), "=r"(r[1]), "=r"(r[2]), "=r"(r[3]) : "r"(addr));
}
__device__ __forceinline__ void mma16816(float* d, const uint32_t* a, const uint32_t* b) {
    asm volatile(
        "mma.sync.aligned.m16n8k16.row.col.f32.bf16.bf16.f32 "
        "{%0,%1,%2,%3}, {%4,%5,%6,%7}, {%8,%9}, {%0,%1,%2,%3};\n"
        : "+f"(d[0]), "+f"(d[1]), "+f"(d[2]), "+f"(d[3])
        : "r"(a[0]), "r"(a[1]), "r"(a[2]), "r"(a[3]), "r"(b[0]), "r"(b[1]));
}
__device__ __forceinline__ uint32_t bf16x2_pack(float a, float b) {
    __nv_bfloat162 p = __nv_bfloat162(__float2bfloat16_rn(a), __float2bfloat16_rn(b));
    return *(uint32_t*)&p;
}
__device__ __forceinline__ float dot8v(float4 a0, float4 a1, const float* m) {
    float t0 = fmaf(a0.y, m[1], a0.x * m[0]);
    float t1 = fmaf(a0.w, m[3], a0.z * m[2]);
    float t2 = fmaf(a1.y, m[5], a1.x * m[4]);
    float t3 = fmaf(a1.w, m[7], a1.z * m[6]);
    return (t0 + t1) + (t2 + t3);
}

#define ASTR 40
#define A_BYTES (128 * ASTR * 2)    // 10240

// ---------------- bf16x3 mma.sync GEMM over one T-segment, templated N-tile ----------------
template<int NT>
__global__ void __launch_bounds__(256, 1)
gemm_bf16x3_mma(const __nv_bfloat16* __restrict__ Ah, const __nv_bfloat16* __restrict__ Al,
                const __nv_bfloat16* __restrict__ Bh, const __nv_bfloat16* __restrict__ Bl,
                const float* __restrict__ bias, float* __restrict__ D, int K, int N, int seg)
{
    constexpr int BSTR_T = NT + 8;
    constexpr int B_BYTES_T = 32 * BSTR_T * 2;
    constexpr int STG_T = 2 * A_BYTES + 2 * B_BYTES_T;
    constexpr int OFF_BH_T = 2 * A_BYTES;
    constexpr int OFF_BL_T = 2 * A_BYTES + B_BYTES_T;
    constexpr int WN  = NT / 4;
    constexpr int NP  = WN / 16;
    constexpr int NTI = WN / 8;

    extern __shared__ char smem[];
    const uint32_t sbase = smem_u32(smem);
    const int tid = threadIdx.x;
    const int lane = tid & 31, w = tid >> 5;
    const int wm = w & 1, wn = w >> 1;
    const int m0 = (blockIdx.y >> 1) * TT + seg * TSEG + (blockIdx.y & 1) * 128;
    const int n0 = blockIdx.x * NT;
    const int NC = K >> 5;

    float acc[4][NTI][4];
#pragma unroll
    for (int i = 0; i < 4; i++)
#pragma unroll
        for (int j = 0; j < NTI; j++)
#pragma unroll
            for (int q = 0; q < 4; q++) acc[i][j][q] = 0.0f;

    const int ar = tid >> 2, as = tid & 3;

    auto load_stage = [&](int s, int c) {
        const uint32_t st = sbase + s * STG_T;
        const long kc = (long)c * 32;
        cp16(st + 0 * A_BYTES + ar * 80 + as * 16,        Ah + (long)(m0 + ar) * K + kc + as * 8);
        cp16(st + 0 * A_BYTES + (ar + 64) * 80 + as * 16, Ah + (long)(m0 + ar + 64) * K + kc + as * 8);
        cp16(st + 1 * A_BYTES + ar * 80 + as * 16,        Al + (long)(m0 + ar) * K + kc + as * 8);
        cp16(st + 1 * A_BYTES + (ar + 64) * 80 + as * 16, Al + (long)(m0 + ar + 64) * K + kc + as * 8);
        if (NT == 128) {
            const int br = tid >> 4, bs = tid & 15;
            cp16(st + OFF_BH_T + br * (BSTR_T * 2) + bs * 16,        Bh + (kc + br) * (long)N + n0 + bs * 8);
            cp16(st + OFF_BH_T + (br + 16) * (BSTR_T * 2) + bs * 16, Bh + (kc + br + 16) * (long)N + n0 + bs * 8);
            cp16(st + OFF_BL_T + br * (BSTR_T * 2) + bs * 16,        Bl + (kc + br) * (long)N + n0 + bs * 8);
            cp16(st + OFF_BL_T + (br + 16) * (BSTR_T * 2) + bs * 16, Bl + (kc + br + 16) * (long)N + n0 + bs * 8);
        } else {
            const int br = tid >> 3, bs = tid & 7;
            cp16(st + OFF_BH_T + br * (BSTR_T * 2) + bs * 16, Bh + (kc + br) * (long)N + n0 + bs * 8);
            cp16(st + OFF_BL_T + br * (BSTR_T * 2) + bs * 16, Bl + (kc + br) * (long)N + n0 + bs * 8);
        }
        asm volatile("cp.async.commit_group;");
    };

    const int pre = (NC < 3) ? NC : 3;
    for (int s = 0; s < pre; s++) load_stage(s, s);

    const uint32_t a_off = (uint32_t)(((wm * 64 + (lane & 15)) * ASTR + ((lane >> 4) << 3)) * 2);
    const uint32_t b_off = (uint32_t)((((lane & 15)) * BSTR_T + wn * WN + ((lane >> 4) << 3)) * 2);

    int s = 0;
    for (int kt = 0; kt < NC; ++kt) {
        const int pend = ((NC - kt) < 3 ? (NC - kt) : 3);
        if (pend == 3)      asm volatile("cp.async.wait_group 2;");
        else if (pend == 2) asm volatile("cp.async.wait_group 1;");
        else                asm volatile("cp.async.wait_group 0;");
        __syncthreads();

        const uint32_t st = sbase + s * STG_T;
        const uint32_t ah_b = st + 0 * A_BYTES + a_off;
        const uint32_t al_b = st + 1 * A_BYTES + a_off;
        const uint32_t bh_b = st + OFF_BH_T + b_off;
        const uint32_t bl_b = st + OFF_BL_T + b_off;

#pragma unroll
        for (int kk = 0; kk < 2; ++kk) {
            uint32_t af[4][4], lf[4][4], bf[NP][4], gf[NP][4];
#pragma unroll
            for (int mt = 0; mt < 4; mt++) {
                ldsm4(af[mt], ah_b + (mt * 16 * ASTR + kk * 16) * 2);
                ldsm4(lf[mt], al_b + (mt * 16 * ASTR + kk * 16) * 2);
            }
#pragma unroll
            for (int np = 0; np < NP; np++) {
                ldsm4t(bf[np], bh_b + (kk * 16 * BSTR_T + np * 16) * 2);
                ldsm4t(gf[np], bl_b + (kk * 16 * BSTR_T + np * 16) * 2);
            }
#pragma unroll
            for (int mt = 0; mt < 4; mt++) {
#pragma unroll
                for (int nt = 0; nt < NTI; nt++) {
                    const uint32_t* bp = &bf[nt >> 1][(nt & 1) * 2];
                    const uint32_t* lp = &gf[nt >> 1][(nt & 1) * 2];
                    mma16816(acc[mt][nt], af[mt], bp);
                    mma16816(acc[mt][nt], lf[mt], bp);
                    mma16816(acc[mt][nt], af[mt], lp);
                }
            }
        }
        __syncthreads();
        const int cn = kt + 3;
        if (cn < NC) load_stage(s, cn);
        if (++s == 3) s = 0;
    }

    const int rb = m0 + wm * 64 + (lane >> 2);
    const int cb = n0 + wn * WN + (lane & 3) * 2;
#pragma unroll
    for (int mt = 0; mt < 4; mt++) {
#pragma unroll
        for (int nt = 0; nt < NTI; nt++) {
            const int r = rb + mt * 16;
            const int c = cb + nt * 8;
            float b0 = 0.0f, b1 = 0.0f;
            if (bias) { b0 = bias[c]; b1 = bias[c + 1]; }
            float2 o0 = make_float2(acc[mt][nt][0] + b0, acc[mt][nt][1] + b1);
            float2 o1 = make_float2(acc[mt][nt][2] + b0, acc[mt][nt][3] + b1);
            *(float2*)(D + (size_t)r * N + c) = o0;
            *(float2*)(D + (size_t)(r + 8) * N + c) = o1;
        }
    }
}

#define GSMEM128 (3 * (2 * A_BYTES + 2 * (32 * 136 * 2)))   // 113664
#define GSMEM64  (3 * (2 * A_BYTES + 2 * (32 * 72 * 2)))    // 89088

// ---------------- conversion / packing kernels ----------------
#define CONV_F4_PER_BATCH (TSEG * DM / 4)       // 65536
__global__ void conv_x_kernel(const float4* __restrict__ src, uint2* __restrict__ dh,
                              uint2* __restrict__ dl, int seg) {
    int i = blockIdx.x * blockDim.x + threadIdx.x;
    if (i >= BB * CONV_F4_PER_BATCH) return;
    int b = i / CONV_F4_PER_BATCH;
    int rem = i - b * CONV_F4_PER_BATCH;
    size_t gi = (size_t)b * (TT * DM / 4) + (size_t)seg * CONV_F4_PER_BATCH + rem;
    float4 v = src[gi];
    float hx = __bfloat162float(__float2bfloat16_rn(v.x));
    float hy = __bfloat162float(__float2bfloat16_rn(v.y));
    float hz = __bfloat162float(__float2bfloat16_rn(v.z));
    float hw = __bfloat162float(__float2bfloat16_rn(v.w));
    uint2 oh, ol;
    oh.x = bf16x2_pack(v.x, v.y); oh.y = bf16x2_pack(v.z, v.w);
    ol.x = bf16x2_pack(v.x - hx, v.y - hy); ol.y = bf16x2_pack(v.z - hz, v.w - hw);
    dh[gi] = oh; dl[gi] = ol;
}

__global__ void pack1b_kernel(const float* __restrict__ Wb, const float* __restrict__ Wdiag,
                              const float* __restrict__ Woff, const float* __restrict__ Walpha) {
    int idx = blockIdx.x * blockDim.x + threadIdx.x;
    if (idx >= DM * NPAD) return;
    int r = idx / NPAD, c = idx - r * NPAD;
    float v;
    if (c < 512)       v = Wb[r * NS + c];
    else if (c < 520)  v = Wdiag[r * 8 + (c - 512)];
    else if (c < 576)  v = Woff[r * 56 + (c - 520)];
    else if (c < 584)  v = Walpha[r * 8 + (c - 576)];
    else               v = 0.0f;
    __nv_bfloat16 h = __float2bfloat16_rn(v);
    g_Wh[idx] = h;
    g_Wl[idx] = __float2bfloat16_rn(v - __bfloat162float(h));
}

__global__ void pack2b_kernel(const float* __restrict__ Wc, const float* __restrict__ bc) {
    int idx = blockIdx.x * blockDim.x + threadIdx.x;
    if (idx >= KHW * DM) return;
    int k = idx >> 10, n = idx & 1023;
    float v;
    if (k < 512)      v = Wc[idx];
    else if (k < 520) v = bc[(size_t)(k - 512) * DM + n];
    else              v = 0.0f;
    __nv_bfloat16 h = __float2bfloat16_rn(v);
    g_W2h[idx] = h;
    g_W2l[idx] = __float2bfloat16_rn(v - __bfloat162float(h));
}

__global__ void misc_kernel(const float* __restrict__ bb, const float* __restrict__ bdiag,
                            const float* __restrict__ boff, const float* __restrict__ balpha,
                            const float* __restrict__ log_lambda) {
    int tid = threadIdx.x;
    if (tid < NS) {
        int k = tid >> 6;
        double dt = 1e-3 * exp((double)k * log(1000.0) / 7.0);
        double ll = (double)log_lambda[tid];
        double sp = log1p(exp(ll));
        g_A[tid] = (float)exp(-dt * sp);
    }
    if (tid < NPAD) {
        float v;
        if (tid < 512)       v = bb[tid];
        else if (tid < 520)  v = bdiag[tid - 512];
        else if (tid < 576)  v = boff[tid - 520];
        else if (tid < 584)  v = balpha[tid - 576];
        else                 v = 0.0f;
        g_bpack[tid] = v;
    }
}

// W_d[r][c] = sum_n V[n,r] * a_n^d * U[n,c]; one block per output, 128-thread reduce.
__global__ void __launch_bounds__(128) wtab_kernel(const float* __restrict__ Uw,
                                                   const float* __restrict__ Vw) {
    __shared__ float warpsum[4];
    const int o = blockIdx.x;               // 0..511
    const int d = o >> 6, r = (o >> 3) & 7, c = o & 7;
    const int t = threadIdx.x;
    float s = 0.0f;
#pragma unroll
    for (int q = 0; q < 4; q++) {
        int n = t + q * 128;
        float a = g_A[n];
        float p = 1.0f;
        for (int e = 0; e < d; e++) p *= a;
        s += Vw[n * 8 + r] * p * Uw[n * 8 + c];
    }
    s += __shfl_xor_sync(0xffffffffu, s, 16);
    s += __shfl_xor_sync(0xffffffffu, s, 8);
    s += __shfl_xor_sync(0xffffffffu, s, 4);
    s += __shfl_xor_sync(0xffffffffu, s, 2);
    s += __shfl_xor_sync(0xffffffffu, s, 1);
    if ((t & 31) == 0) warpsum[t >> 5] = s;
    __syncthreads();
    if (t == 0)
        g_W8[o] = (warpsum[0] + warpsum[1]) + (warpsum[2] + warpsum[3]);
}

// ---------------- activations for one T-segment ----------------
__global__ void __launch_bounds__(256) act_kernel(int seg) {
    __shared__ float s[64 * 72];
    const int row0 = (blockIdx.x >> 2) * TT + seg * TSEG + (blockIdx.x & 3) * 64;
    const int tid = threadIdx.x;
    for (int i = tid; i < 64 * 72; i += 256) {
        int r = i / 72, c = i - r * 72;
        s[i] = g_P[(size_t)(row0 + r) * NPAD + 512 + c];
    }
    __syncthreads();
    if (tid < 64) {
        const int row = row0 + tid;
        const float* v = &s[tid * 72];
        float dg[8];
#pragma unroll
        for (int i = 0; i < 8; i++) dg[i] = 1.0f / (1.0f + expf(-v[i]));
        float Cm[64];
        int m = 0;
#pragma unroll
        for (int i = 0; i < 8; i++) {
#pragma unroll
            for (int j = 0; j < 8; j++) {
                if (i == j) {
                    Cm[i * 8 + j] = dg[i];
                } else {
                    float x = v[8 + m];
                    float sp = (x > 15.0f) ? x : log1pf(expf(x));
                    Cm[i * 8 + j] = -sp;
                    m++;
                }
            }
        }
#pragma unroll
        for (int q = 0; q < 64; q++) g_C[(size_t)row * 64 + q] = Cm[q];
        float a[8], mx = v[64];
#pragma unroll
        for (int i = 1; i < 8; i++) mx = fmaxf(mx, v[64 + i]);
        float sum = 0.0f;
#pragma unroll
        for (int i = 0; i < 8; i++) { a[i] = expf(v[64 + i] - mx); sum += a[i]; }
        float inv = 1.0f / sum;
#pragma unroll
        for (int k = 0; k < 8; k++) {
            float al = a[k] * inv;
            g_alpha[(size_t)row * 8 + k] = al;
            __nv_bfloat16 h = __float2bfloat16_rn(al);
            g_hwh[(size_t)row * KHW + 512 + k] = h;
            g_hwl[(size_t)row * KHW + 512 + k] = __float2bfloat16_rn(al - __bfloat162float(h));
        }
    }
    const __nv_bfloat16 z = __float2bfloat16_rn(0.0f);
    for (int i = tid; i < 64 * 56; i += 256) {
        int r = i / 56, c = i - r * 56;
        g_hwh[(size_t)(row0 + r) * KHW + 520 + c] = z;
        g_hwl[(size_t)(row0 + r) * KHW + 520 + c] = z;
    }
}

// ---------------- chunked scan over one T-segment (unchanged from R15) ----------------
#define SCAN_SMEM (19840 * 4)
__global__ void __launch_bounds__(512, 1) scan_kernel(const float* __restrict__ Uw,
                                                      const float* __restrict__ Vw, int seg) {
    extern __shared__ float sm[];
    float* bxs  = sm;
    float* fbuf = sm + 12288;
    float* cst  = sm + 16384;
    float* ast  = sm + 17920;
    float* wt   = sm + 18112;
    float* red  = sm + 18624;
    float* pf   = sm + 19648;
    float* mb   = sm + 19712;

    const int b = blockIdx.x;
    const int i = threadIdx.x;
    const int wid = i >> 5, lane = i & 31;
    const uint32_t sbase = smem_u32(sm);
    const int cbeg = seg * CH_PER_SEG;

    float hreg = (seg == 0) ? 0.0f : g_hcarry[b * NS + i];
    wt[i] = g_W8[i];
    const int k = i & 7, g8 = i >> 3;
    float Vv[8], Urow[8];
#pragma unroll
    for (int q = 0; q < 8; q++) Vv[q] = Vw[(g8 * 8 + q) * 8 + k];
#pragma unroll
    for (int q = 0; q < 8; q++) Urow[q] = Uw[i * 8 + q];
    const float an = g_A[i];
    float wreg[8];
    if (seg == 0) {
#pragma unroll
        for (int q = 0; q < 8; q++) wreg[q] = 0.0f;
    } else {
#pragma unroll
        for (int q = 0; q < 8; q++) wreg[q] = g_wcarry[b * 8 + q];
    }

    const float* bxg = g_P + (size_t)b * TT * NPAD;
    const float* cg  = g_C + (size_t)b * TT * 64;
    const float* ag  = g_alpha + (size_t)b * TT * 8;
    const size_t t0 = (size_t)cbeg * 8;

    for (int g = 0; g < 2; g++) {
        const size_t tb = t0 + (size_t)g * 8;
        for (int idx = i; idx < 1024; idx += 512) {
            int t = idx >> 7, sg = idx & 127;
            cp16(sbase + (uint32_t)(g * 4096 + t * 512 + sg * 4) * 4, bxg + (tb + t) * NPAD + sg * 4);
        }
        for (int idx = i; idx < 128; idx += 512) {
            int t = idx >> 4, sg = idx & 15;
            cp16(sbase + (uint32_t)(16384 + g * 512 + t * 64 + sg * 4) * 4, cg + (tb + t) * 64 + sg * 4);
        }
        if (i < 16) {
            int t = i >> 1, sg = i & 1;
            cp16(sbase + (uint32_t)(17920 + g * 64 + t * 8 + sg * 4) * 4, ag + (tb + t) * 8 + sg * 4);
        }
        asm volatile("cp.async.commit_group;");
    }
    asm volatile("cp.async.wait_group 0;");
    __syncthreads();

    float ff[8];
    for (int cc = 0; cc < CH_PER_SEG; ++cc) {
        const int buf = cc % 3;
        float fp = hreg;
#pragma unroll
        for (int j = 0; j < 8; j++) {
            fp = fmaf(an, fp, bxs[buf * 4096 + j * 512 + i]);
            ff[j] = fp;
            fbuf[j * 512 + i] = fp;
        }
        __syncwarp();

        float pv[8];
        {
            const float* fb = fbuf + g8 * 8;
#pragma unroll
            for (int j = 0; j < 8; j++) {
                float4 f0 = *(const float4*)(fb + j * 512);
                float4 f1 = *(const float4*)(fb + j * 512 + 4);
                pv[j] = dot8v(f0, f1, Vv);
            }
        }
#pragma unroll
        for (int j = 0; j < 8; j++) {
            pv[j] += __shfl_xor_sync(0xffffffffu, pv[j], 8);
            pv[j] += __shfl_xor_sync(0xffffffffu, pv[j], 16);
        }
        if (lane < 8) {
#pragma unroll
            for (int j = 0; j < 8; j++) red[wid * 64 + j * 8 + lane] = pv[j];
        }
        __syncthreads();

        bool issued = false;
        if (i >= 128 && cc + 2 < CH_PER_SEG) {
            const int nb = (cc + 2) % 3;
            const size_t tb = t0 + (size_t)(cc + 2) * 8;
            const int tt = i - 128;
            for (int idx = tt; idx < 1024; idx += 384) {
                int t = idx >> 7, sg = idx & 127;
                cp16(sbase + (uint32_t)(nb * 4096 + t * 512 + sg * 4) * 4,
                     bxg + (tb + t) * NPAD + sg * 4);
            }
            for (int idx = tt; idx < 128; idx += 384) {
                int t = idx >> 4, sg = idx & 15;
                cp16(sbase + (uint32_t)(16384 + nb * 512 + t * 64 + sg * 4) * 4,
                     cg + (tb + t) * 64 + sg * 4);
            }
            if (tt < 16) {
                int t = tt >> 1, sg = tt & 1;
                cp16(sbase + (uint32_t)(17920 + nb * 64 + t * 8 + sg * 4) * 4,
                     ag + (tb + t) * 8 + sg * 4);
            }
            asm volatile("cp.async.commit_group;");
            issued = true;
        }

        if (wid == 0) {
#pragma unroll
            for (int q = 0; q < 2; q++) {
                const int o = lane + q * 32;
                float s0 = 0.0f, s1 = 0.0f, s2 = 0.0f, s3 = 0.0f;
#pragma unroll
                for (int w4 = 0; w4 < 4; w4++) {
                    s0 += red[(w4 * 4 + 0) * 64 + o];
                    s1 += red[(w4 * 4 + 1) * 64 + o];
                    s2 += red[(w4 * 4 + 2) * 64 + o];
                    s3 += red[(w4 * 4 + 3) * 64 + o];
                }
                pf[o] = (s0 + s1) + (s2 + s3);
            }
            __syncwarp();

            const int r = lane & 7, dup = lane >> 3;
            const int j1 = dup, j2 = dup + 4;
            float PFr[8];
#pragma unroll
            for (int s = 0; s < 8; s++) PFr[s] = pf[s * 8 + r];
            const float* cb = cst + buf * 512;
            float4 c0 = *(const float4*)(cb + r * 8);
            float4 c1 = *(const float4*)(cb + r * 8 + 4);
            float accA = 0.0f, accB = 0.0f;
            float* mbw = mb + (cc & 1) * 64;
#pragma unroll
            for (int s = 0; s < 8; s++) {
                float4 n0, n1;
                if (s < 7) {
                    n0 = *(const float4*)(cb + (s + 1) * 64 + r * 8);
                    n1 = *(const float4*)(cb + (s + 1) * 64 + r * 8 + 4);
                }
                float mr = dot8v(c0, c1, wreg);
                float mf[8];
#pragma unroll
                for (int q = 0; q < 8; q++) mf[q] = __shfl_sync(0xffffffffu, mr, q + (dup << 3));
                if (j1 >= s) {
                    const float* wr = wt + (j1 - s) * 64 + r * 8;
                    accA += dot8v(*(const float4*)wr, *(const float4*)(wr + 4), mf);
                }
                if (j2 >= s) {
                    const float* wr = wt + (j2 - s) * 64 + r * 8;
                    accB += dot8v(*(const float4*)wr, *(const float4*)(wr + 4), mf);
                }
                float wv = (j1 == s) ? (PFr[s] + accA) : ((j2 == s) ? (PFr[s] + accB) : 0.0f);
#pragma unroll
                for (int q = 0; q < 8; q++) wreg[q] = __shfl_sync(0xffffffffu, wv, q + ((s & 3) << 3));
                if (dup == 0) mbw[s * 8 + r] = mr;
                c0 = n0; c1 = n1;
            }
        } else if (i >= 128) {
            if (issued) asm volatile("cp.async.wait_group 1;");
            else        asm volatile("cp.async.wait_group 0;");
        }
        __syncthreads();

        {
            float g = 0.0f;
            const size_t row0 = (size_t)b * TT + (size_t)(cbeg + cc) * 8;
            __nv_bfloat16* oh = g_hwh + row0 * KHW + i;
            __nv_bfloat16* ol = g_hwl + row0 * KHW + i;
            const float* mbr = mb + (cc & 1) * 64;
            const float* as_ = ast + buf * 64;
            const int ab = i >> 6;
#pragma unroll
            for (int j = 0; j < 8; j++) {
                float4 m0 = *(const float4*)(mbr + j * 8);
                float4 m1 = *(const float4*)(mbr + j * 8 + 4);
                float um = dot8v(m0, m1, Urow);
                g = fmaf(an, g, um);
                float h = ff[j] + g;
                float wv = h * as_[j * 8 + ab];
                __nv_bfloat16 hi = __float2bfloat16_rn(wv);
                oh[(size_t)j * KHW] = hi;
                ol[(size_t)j * KHW] = __float2bfloat16_rn(wv - __bfloat162float(hi));
                if (j == 7) hreg = h;
            }
        }
    }

    g_hcarry[b * NS + i] = hreg;
    if (wid == 0 && lane == 0) {
#pragma unroll
        for (int q = 0; q < 8; q++) g_wcarry[b * 8 + q] = wreg[q];
    }
}

// ---------------- launch: 8-segment pipeline, 3 streams, proper capture fork ----------------
extern "C" void kernel_launch(void* const* d_in, const int* in_sizes, int n_in,
                              void* d_out, int out_size) {
    const float* x      = (const float*)d_in[0];
    const float* Wb     = (const float*)d_in[1];
    const float* bb     = (const float*)d_in[2];
    const float* Wdiag  = (const float*)d_in[3];
    const float* bdiag  = (const float*)d_in[4];
    const float* Woff   = (const float*)d_in[5];
    const float* boff   = (const float*)d_in[6];
    const float* Walpha = (const float*)d_in[7];
    const float* balpha = (const float*)d_in[8];
    const float* Wc     = (const float*)d_in[9];
    const float* bc     = (const float*)d_in[10];
    const float* ll     = (const float*)d_in[11];
    const float* U      = (const float*)d_in[12];
    const float* V      = (const float*)d_in[13];
    float* out = (float*)d_out;

    float *pP, *pbpack;
    __nv_bfloat16 *pxh, *pxl, *pWh, *pWl, *phwh, *phwl, *pW2h, *pW2l;
    cudaGetSymbolAddress((void**)&pP,     g_P);
    cudaGetSymbolAddress((void**)&pbpack, g_bpack);
    cudaGetSymbolAddress((void**)&pxh,    g_xh);
    cudaGetSymbolAddress((void**)&pxl,    g_xl);
    cudaGetSymbolAddress((void**)&pWh,    g_Wh);
    cudaGetSymbolAddress((void**)&pWl,    g_Wl);
    cudaGetSymbolAddress((void**)&phwh,   g_hwh);
    cudaGetSymbolAddress((void**)&phwl,   g_hwl);
    cudaGetSymbolAddress((void**)&pW2h,   g_W2h);
    cudaGetSymbolAddress((void**)&pW2l,   g_W2l);

    cudaFuncSetAttribute(gemm_bf16x3_mma<128>, cudaFuncAttributeMaxDynamicSharedMemorySize, GSMEM128);
    cudaFuncSetAttribute(gemm_bf16x3_mma<64>,  cudaFuncAttributeMaxDynamicSharedMemorySize, GSMEM64);
    cudaFuncSetAttribute(scan_kernel, cudaFuncAttributeMaxDynamicSharedMemorySize, SCAN_SMEM);

    static cudaStream_t sB = nullptr, sC = nullptr;
    static cudaEvent_t evA[NSEG], evS[NSEG], evC[NSEG];
    static cudaEvent_t evRoot = nullptr, evM = nullptr, evEnd = nullptr;
    static int streams_ok = -1;
    if (streams_ok < 0) {
        bool ok = (cudaStreamCreateWithFlags(&sB, cudaStreamNonBlocking) == cudaSuccess) &&
                  (cudaStreamCreateWithFlags(&sC, cudaStreamNonBlocking) == cudaSuccess);
        for (int s = 0; s < NSEG && ok; s++) {
            ok = (cudaEventCreateWithFlags(&evA[s], cudaEventDisableTiming) == cudaSuccess) &&
                 (cudaEventCreateWithFlags(&evS[s], cudaEventDisableTiming) == cudaSuccess) &&
                 (cudaEventCreateWithFlags(&evC[s], cudaEventDisableTiming) == cudaSuccess);
        }
        ok = ok && (cudaEventCreateWithFlags(&evRoot, cudaEventDisableTiming) == cudaSuccess);
        ok = ok && (cudaEventCreateWithFlags(&evM, cudaEventDisableTiming) == cudaSuccess);
        ok = ok && (cudaEventCreateWithFlags(&evEnd, cudaEventDisableTiming) == cudaSuccess);
        streams_ok = ok ? 1 : 0;
    }

    const int conv_blocks = (BB * CONV_F4_PER_BATCH + 255) / 256;

    if (streams_ok == 1) {
        // fork side streams from the capture-origin stream FIRST
        cudaEventRecord(evRoot, 0);
        cudaStreamWaitEvent(sB, evRoot, 0);
        cudaStreamWaitEvent(sC, evRoot, 0);

        // sC (captured): pack2b + all conv segments (off the GEMM1 spine)
        pack2b_kernel<<<(KHW * DM + 255) / 256, 256, 0, sC>>>(Wc, bc);
        for (int s = 0; s < NSEG; s++) {
            conv_x_kernel<<<conv_blocks, 256, 0, sC>>>((const float4*)x, (uint2*)pxh, (uint2*)pxl, s);
            cudaEventRecord(evC[s], sC);
        }
        // stream 0: weight pack + misc
        pack1b_kernel<<<(DM * NPAD + 255) / 256, 256>>>(Wb, Wdiag, Woff, Walpha);
        misc_kernel<<<1, 1024>>>(bb, bdiag, boff, balpha, ll);
        cudaEventRecord(evM, 0);
        cudaStreamWaitEvent(sB, evM, 0);
        wtab_kernel<<<512, 128, 0, sB>>>(U, V);

        // producer chain on stream 0: GEMM1 (NT=64, 160 CTAs) + act
        for (int s = 0; s < NSEG; s++) {
            cudaStreamWaitEvent(0, evC[s], 0);
            gemm_bf16x3_mma<64><<<dim3(NPAD / 64, 16), 256, GSMEM64>>>(pxh, pxl, pWh, pWl,
                                                                       pbpack, pP, DM, NPAD, s);
            act_kernel<<<32, 256>>>(s);
            cudaEventRecord(evA[s], 0);
        }
        // scan chain on stream B
        for (int s = 0; s < NSEG; s++) {
            cudaStreamWaitEvent(sB, evA[s], 0);
            scan_kernel<<<BB, 512, SCAN_SMEM, sB>>>(U, V, s);
            cudaEventRecord(evS[s], sB);
        }
        // GEMM2 chain on stream C (NT=128)
        for (int s = 0; s < NSEG; s++) {
            cudaStreamWaitEvent(sC, evS[s], 0);
            gemm_bf16x3_mma<128><<<dim3(DM / 128, 16), 256, GSMEM128, sC>>>(phwh, phwl, pW2h, pW2l,
                                                                            nullptr, out, KHW, DM, s);
        }
        cudaEventRecord(evEnd, sC);
        cudaStreamWaitEvent(0, evEnd, 0);
    } else {
        // sequential fallback on stream 0
        pack2b_kernel<<<(KHW * DM + 255) / 256, 256>>>(Wc, bc);
        pack1b_kernel<<<(DM * NPAD + 255) / 256, 256>>>(Wb, Wdiag, Woff, Walpha);
        misc_kernel<<<1, 1024>>>(bb, bdiag, boff, balpha, ll);
        wtab_kernel<<<512, 128>>>(U, V);
        for (int s = 0; s < NSEG; s++) {
            conv_x_kernel<<<conv_blocks, 256>>>((const float4*)x, (uint2*)pxh, (uint2*)pxl, s);
            gemm_bf16x3_mma<64><<<dim3(NPAD / 64, 16), 256, GSMEM64>>>(pxh, pxl, pWh, pWl,
                                                                       pbpack, pP, DM, NPAD, s);
            act_kernel<<<32, 256>>>(s);
        }
        for (int s = 0; s < NSEG; s++) scan_kernel<<<BB, 512, SCAN_SMEM>>>(U, V, s);
        for (int s = 0; s < NSEG; s++)
            gemm_bf16x3_mma<128><<<dim3(DM / 128, 16), 256, GSMEM128>>>(phwh, phwl, pW2h, pW2l,
                                                                        nullptr, out, KHW, DM, s);
    }
}